// round 12
// baseline (speedup 1.0000x reference)
#include <cuda_runtime.h>
#include <cuda_bf16.h>

#define MTOT (256*256)

// Scratch (static device arrays — no allocation in kernel_launch)
__device__ __nv_bfloat16 g_qkvg[(size_t)MTOT * 512];  // [m][q|k|v|g] bf16
__device__ __nv_bfloat16 g_attn[(size_t)MTOT * 128];  // gated attn out bf16
__device__ __nv_bfloat16 g_Wbf[512 * 128];            // W_qkvg bf16, [n=512][k=128]
__device__ float         g_Wot[128 * 128];            // W_o transposed fp32 [k][n]

// ---------------------------------------------------------------------------
// helpers
// ---------------------------------------------------------------------------
__device__ __forceinline__ unsigned f2tf(float x) {
    unsigned u;
    asm("cvt.rna.tf32.f32 %0, %1;" : "=r"(u) : "f"(x));
    return u;
}
__device__ __forceinline__ float f2tff(float x) { return __uint_as_float(f2tf(x)); }
__device__ __forceinline__ float bf_lo(unsigned w) { return __uint_as_float(w << 16); }
__device__ __forceinline__ float bf_hi(unsigned w) { return __uint_as_float(w & 0xffff0000u); }

__device__ __forceinline__ void mma_tf32(float* d, const unsigned* a, const unsigned* b) {
    asm volatile(
        "mma.sync.aligned.m16n8k8.row.col.f32.tf32.tf32.f32 "
        "{%0,%1,%2,%3}, {%4,%5,%6,%7}, {%8,%9}, {%0,%1,%2,%3};"
        : "+f"(d[0]), "+f"(d[1]), "+f"(d[2]), "+f"(d[3])
        : "r"(a[0]), "r"(a[1]), "r"(a[2]), "r"(a[3]),
          "r"(b[0]), "r"(b[1]));
}
__device__ __forceinline__ void mma_bf16(float* d, const unsigned* a, const unsigned* b) {
    asm volatile(
        "mma.sync.aligned.m16n8k16.row.col.f32.bf16.bf16.f32 "
        "{%0,%1,%2,%3}, {%4,%5,%6,%7}, {%8,%9}, {%0,%1,%2,%3};"
        : "+f"(d[0]), "+f"(d[1]), "+f"(d[2]), "+f"(d[3])
        : "r"(a[0]), "r"(a[1]), "r"(a[2]), "r"(a[3]),
          "r"(b[0]), "r"(b[1]));
}
__device__ __forceinline__ void ldsm_x4(unsigned& r0, unsigned& r1, unsigned& r2,
                                        unsigned& r3, unsigned addr) {
    asm volatile("ldmatrix.sync.aligned.m8n8.x4.shared.b16 {%0,%1,%2,%3}, [%4];"
        : "=r"(r0), "=r"(r1), "=r"(r2), "=r"(r3) : "r"(addr));
}

// ---------------------------------------------------------------------------
// K0: quantize W_qkvg to bf16 + fp32 transpose of W_o.
// ---------------------------------------------------------------------------
__global__ __launch_bounds__(256) void prep_w_kernel(
    const float* __restrict__ W, const float* __restrict__ Wo)
{
    int idx = blockIdx.x * 256 + threadIdx.x;
    if (idx < 512 * 128) {
        g_Wbf[idx] = __float2bfloat16_rn(W[idx]);
    }
    int idx2 = idx - 512 * 128;
    if (idx2 >= 0 && idx2 < 128 * 128) {
        int k = idx2 >> 7;
        int n = idx2 & 127;
        g_Wot[idx2] = Wo[n * 128 + k];
    }
}

// ---------------------------------------------------------------------------
// K1: QKVG projection, bf16 m16n8k16 MMA + ldmatrix fragment feed.
// Block = 128 m x N=512 (2 chunks of 256), 512 threads, warp tile 32x64.
// smem: As[128][68w] | Bs[512][68w]  (bf16-pair words, 4-word row pad)
// ---------------------------------------------------------------------------
#define KW 68

__global__ __launch_bounds__(512, 1) void gemm_qkvg_bf_kernel(const float* __restrict__ X)
{
    extern __shared__ unsigned shm[];
    unsigned* As = shm;              // [128][KW]
    unsigned* Bs = shm + 128 * KW;   // [512][KW]

    const int tid  = threadIdx.x;
    const int lane = tid & 31;
    const int w    = tid >> 5;
    const int g    = lane >> 2;
    const int t    = lane & 3;
    const int mw   = (w & 3) * 32;
    const int nw   = (w >> 2) * 64;

    const int m0 = blockIdx.x * 128;

    // stage A: X fp32 -> bf16x2 words
    for (int l = tid; l < 4096; l += 512) {
        int r = l >> 5, c4 = (l & 31) << 2;
        float4 v = *(const float4*)&X[(size_t)(m0 + r) * 128 + c4];
        __nv_bfloat162 p0 = __float22bfloat162_rn(make_float2(v.x, v.y));
        __nv_bfloat162 p1 = __float22bfloat162_rn(make_float2(v.z, v.w));
        As[r * KW + (c4 >> 1)]     = *(unsigned*)&p0;
        As[r * KW + (c4 >> 1) + 1] = *(unsigned*)&p1;
    }
    // stage B: g_Wbf rows (128 bf16 = 16 uint4 per row), 512 rows
    for (int l = tid; l < 8192; l += 512) {
        int n = l >> 4, q = l & 15;
        uint4 v = *(const uint4*)&g_Wbf[n * 128 + q * 8];
        *(uint4*)&Bs[n * KW + q * 4] = v;
    }
    __syncthreads();

    // ldmatrix lane address bases
    const unsigned as_s = (unsigned)__cvta_generic_to_shared(As);
    const unsigned bs_s = (unsigned)__cvta_generic_to_shared(Bs);
    const unsigned aAddr0 = as_s + (((mw + (lane & 15)) * KW) + ((lane & 16) ? 4 : 0)) * 4;
    const unsigned aAddr1 = aAddr0 + 16 * KW * 4;
    const unsigned bLane  = bs_s + ((((lane & 7) + ((lane & 16) ? 8 : 0)) * KW)
                                    + ((lane & 8) ? 4 : 0)) * 4;

    #pragma unroll
    for (int chunk = 0; chunk < 2; chunk++) {
        const int nbase = chunk * 256;
        float acc[2][8][4];
        #pragma unroll
        for (int i = 0; i < 2; i++)
            #pragma unroll
            for (int j = 0; j < 8; j++)
                #pragma unroll
                for (int c = 0; c < 4; c++) acc[i][j][c] = 0.f;

        #pragma unroll
        for (int kw = 0; kw < 64; kw += 8) {   // k-step of 16 bf16 (8 words)
            unsigned a[2][4], b[8][2];
            ldsm_x4(a[0][0], a[0][1], a[0][2], a[0][3], aAddr0 + kw * 4);
            ldsm_x4(a[1][0], a[1][1], a[1][2], a[1][3], aAddr1 + kw * 4);
            #pragma unroll
            for (int fnp = 0; fnp < 4; fnp++) {
                unsigned addr = bLane + (((nbase + nw + 16 * fnp) * KW) + kw) * 4;
                ldsm_x4(b[2*fnp][0], b[2*fnp][1], b[2*fnp+1][0], b[2*fnp+1][1], addr);
            }
            #pragma unroll
            for (int fm = 0; fm < 2; fm++)
                #pragma unroll
                for (int fn = 0; fn < 8; fn++)
                    mma_bf16(acc[fm][fn], a[fm], b[fn]);
        }

        // epilogue: bf16 stores
        #pragma unroll
        for (int fm = 0; fm < 2; fm++) {
            int row = m0 + mw + fm * 16 + g;
            #pragma unroll
            for (int fn = 0; fn < 8; fn++) {
                int col = nbase + nw + fn * 8 + 2 * t;
                __nv_bfloat162 lo = __float22bfloat162_rn(make_float2(acc[fm][fn][0], acc[fm][fn][1]));
                __nv_bfloat162 hi = __float22bfloat162_rn(make_float2(acc[fm][fn][2], acc[fm][fn][3]));
                *(__nv_bfloat162*)&g_qkvg[(size_t)row * 512 + col] = lo;
                *(__nv_bfloat162*)&g_qkvg[(size_t)(row + 8) * 512 + col] = hi;
            }
        }
    }
}

// ---------------------------------------------------------------------------
// K2: fused attention.  QK^T in bf16 (exact: inputs are bf16) + ldmatrix;
// scale applied exactly in fp32 on S.  P*V stays tf32 (precision).
// smem words: KsW[256][20] | QsW[256][20] | VsT f32[32][268] | Ps f32[256][36]
//             | madd f32[256]   (~113 KB)
// ---------------------------------------------------------------------------
#define KQ_STRIDE 20
#define KS_STRIDE 36
#define VT_STRIDE 268

__global__ __launch_bounds__(256) void attn_tc_kernel(
    const float* __restrict__ mask, const float* __restrict__ bias,
    const float* __restrict__ gbias)
{
    extern __shared__ unsigned shu[];
    unsigned* KsW = shu;                         // [256][20] bf16-pair words
    unsigned* QsW = KsW + 256 * KQ_STRIDE;       // [256][20]
    float* VsT  = (float*)(QsW + 256 * KQ_STRIDE); // [32][268]
    float* Ps   = VsT + 32 * VT_STRIDE;          // [256][36]
    float* madd = Ps + 256 * KS_STRIDE;          // [256]

    const int h = blockIdx.x;
    const int b = blockIdx.y;
    const int tid  = threadIdx.x;
    const int lane = tid & 31;
    const int w    = tid >> 5;
    const int g    = lane >> 2;
    const int t    = lane & 3;
    const int q0   = w * 32;

    {
        const __nv_bfloat16* base = &g_qkvg[(size_t)(b * 256 + tid) * 512 + h * 32];
        // K raw bf16 words
        #pragma unroll
        for (int j = 0; j < 4; j++) {
            uint4 u = *(const uint4*)(base + 128 + j * 8);
            unsigned* d = &KsW[tid * KQ_STRIDE + j * 4];
            d[0] = u.x; d[1] = u.y; d[2] = u.z; d[3] = u.w;
        }
        // Q raw bf16 words (scale applied later in fp32, exactly)
        #pragma unroll
        for (int j = 0; j < 4; j++) {
            uint4 u = *(const uint4*)(base + j * 8);
            unsigned* d = &QsW[tid * KQ_STRIDE + j * 4];
            d[0] = u.x; d[1] = u.y; d[2] = u.z; d[3] = u.w;
        }
        // V rows -> transposed fp32 scatter (exact bf16->f32)
        #pragma unroll
        for (int j = 0; j < 4; j++) {
            uint4 u = *(const uint4*)(base + 256 + j * 8);
            VsT[(j * 8 + 0) * VT_STRIDE + tid] = bf_lo(u.x);
            VsT[(j * 8 + 1) * VT_STRIDE + tid] = bf_hi(u.x);
            VsT[(j * 8 + 2) * VT_STRIDE + tid] = bf_lo(u.y);
            VsT[(j * 8 + 3) * VT_STRIDE + tid] = bf_hi(u.y);
            VsT[(j * 8 + 4) * VT_STRIDE + tid] = bf_lo(u.z);
            VsT[(j * 8 + 5) * VT_STRIDE + tid] = bf_hi(u.z);
            VsT[(j * 8 + 6) * VT_STRIDE + tid] = bf_lo(u.w);
            VsT[(j * 8 + 7) * VT_STRIDE + tid] = bf_hi(u.w);
        }
        madd[tid] = (mask[(size_t)b * 256 + tid] - 1.0f) * 1e9f;
    }
    __syncthreads();

    // Q bf16 fragments (A operand, m16n8k16): [mf][ks in 0..1][4]
    unsigned Qa[2][2][4];
    #pragma unroll
    for (int mf = 0; mf < 2; mf++) {
        int r = q0 + 16 * mf + g;
        #pragma unroll
        for (int ks = 0; ks < 2; ks++) {
            Qa[mf][ks][0] = QsW[r * KQ_STRIDE + ks * 8 + t];
            Qa[mf][ks][1] = QsW[(r + 8) * KQ_STRIDE + ks * 8 + t];
            Qa[mf][ks][2] = QsW[r * KQ_STRIDE + ks * 8 + t + 4];
            Qa[mf][ks][3] = QsW[(r + 8) * KQ_STRIDE + ks * 8 + t + 4];
        }
    }
    __syncwarp();

    const unsigned ks_s = (unsigned)__cvta_generic_to_shared(KsW);
    const unsigned kLane = ks_s + ((((lane & 7) + ((lane & 16) ? 8 : 0)) * KQ_STRIDE)
                                   + ((lane & 8) ? 4 : 0)) * 4;

    float Oacc[2][4][4];
    #pragma unroll
    for (int i = 0; i < 2; i++)
        #pragma unroll
        for (int j = 0; j < 4; j++)
            #pragma unroll
            for (int c = 0; c < 4; c++) Oacc[i][j][c] = 0.f;
    float lsum[4] = {0.f, 0.f, 0.f, 0.f};

    float* Pw = Ps + q0 * KS_STRIDE;
    const float* biasw = &bias[((size_t)h * 256 + q0) * 256];
    const float SC = 0.17677669529663687f;

    for (int k0 = 0; k0 < 256; k0 += 32) {
        // ---- S = Q K^T : bf16 MMA, exact on bf16 inputs ----
        float Sacc[2][4][4];
        #pragma unroll
        for (int i = 0; i < 2; i++)
            #pragma unroll
            for (int j = 0; j < 4; j++)
                #pragma unroll
                for (int c = 0; c < 4; c++) Sacc[i][j][c] = 0.f;

        #pragma unroll
        for (int ks = 0; ks < 2; ks++) {
            unsigned bf[4][2];
            #pragma unroll
            for (int nfp = 0; nfp < 2; nfp++) {
                unsigned addr = kLane + (((k0 + 16 * nfp) * KQ_STRIDE) + ks * 8) * 4;
                ldsm_x4(bf[2*nfp][0], bf[2*nfp][1], bf[2*nfp+1][0], bf[2*nfp+1][1], addr);
            }
            #pragma unroll
            for (int mf = 0; mf < 2; mf++)
                #pragma unroll
                for (int nf = 0; nf < 4; nf++)
                    mma_bf16(Sacc[mf][nf], Qa[mf][ks], bf[nf]);
        }

        // ---- exp(S*scale + mask + bias), row sums, store P (tf32) ----
        #pragma unroll
        for (int nf = 0; nf < 4; nf++) {
            int col = k0 + 8 * nf + 2 * t;
            float2 md = *(const float2*)&madd[col];
            #pragma unroll
            for (int mf = 0; mf < 2; mf++) {
                int rloc = 16 * mf + g;
                float2 bz0 = *(const float2*)&biasw[(size_t)rloc * 256 + col];
                float2 bz1 = *(const float2*)&biasw[(size_t)(rloc + 8) * 256 + col];
                float p00 = __expf(fmaf(Sacc[mf][nf][0], SC, md.x + bz0.x));
                float p01 = __expf(fmaf(Sacc[mf][nf][1], SC, md.y + bz0.y));
                float p10 = __expf(fmaf(Sacc[mf][nf][2], SC, md.x + bz1.x));
                float p11 = __expf(fmaf(Sacc[mf][nf][3], SC, md.y + bz1.y));
                lsum[mf * 2 + 0] += p00 + p01;
                lsum[mf * 2 + 1] += p10 + p11;
                float2 s0 = { f2tff(p00), f2tff(p01) };
                float2 s1 = { f2tff(p10), f2tff(p11) };
                *(float2*)&Pw[rloc * KS_STRIDE + 8 * nf + 2 * t] = s0;
                *(float2*)&Pw[(rloc + 8) * KS_STRIDE + 8 * nf + 2 * t] = s1;
            }
        }
        __syncwarp();

        // ---- O += P V  (tf32, unchanged) ----
        #pragma unroll
        for (int ks = 0; ks < 4; ks++) {
            unsigned af[2][4], bf[4][2];
            #pragma unroll
            for (int mf = 0; mf < 2; mf++) {
                int rloc = 16 * mf + g;
                af[mf][0] = __float_as_uint(Pw[rloc * KS_STRIDE + 8 * ks + t]);
                af[mf][1] = __float_as_uint(Pw[(rloc + 8) * KS_STRIDE + 8 * ks + t]);
                af[mf][2] = __float_as_uint(Pw[rloc * KS_STRIDE + 8 * ks + t + 4]);
                af[mf][3] = __float_as_uint(Pw[(rloc + 8) * KS_STRIDE + 8 * ks + t + 4]);
            }
            #pragma unroll
            for (int nf = 0; nf < 4; nf++) {
                bf[nf][0] = __float_as_uint(VsT[(8 * nf + g) * VT_STRIDE + k0 + 8 * ks + t]);
                bf[nf][1] = __float_as_uint(VsT[(8 * nf + g) * VT_STRIDE + k0 + 8 * ks + t + 4]);
            }
            #pragma unroll
            for (int mf = 0; mf < 2; mf++)
                #pragma unroll
                for (int nf = 0; nf < 4; nf++)
                    mma_tf32(Oacc[mf][nf], af[mf], bf[nf]);
        }
        __syncwarp();
    }

    float inv[4];
    #pragma unroll
    for (int j = 0; j < 4; j++) {
        float l = lsum[j];
        l += __shfl_xor_sync(0xffffffff, l, 1);
        l += __shfl_xor_sync(0xffffffff, l, 2);
        inv[j] = 1.0f / l;
    }

    #pragma unroll
    for (int mf = 0; mf < 2; mf++) {
        #pragma unroll
        for (int half = 0; half < 2; half++) {
            int r = q0 + 16 * mf + g + half * 8;
            float iv = inv[mf * 2 + half];
            const __nv_bfloat16* grow = &g_qkvg[(size_t)(b * 256 + r) * 512 + 384 + h * 32];
            __nv_bfloat16* orow = &g_attn[(size_t)(b * 256 + r) * 128 + h * 32];
            #pragma unroll
            for (int nf = 0; nf < 4; nf++) {
                int c = 8 * nf + 2 * t;
                unsigned gw = *(const unsigned*)(grow + c);
                float2 gb = *(const float2*)&gbias[h * 32 + c];
                float g0 = bf_lo(gw) + gb.x;
                float g1 = bf_hi(gw) + gb.y;
                float ox = Oacc[mf][nf][half * 2 + 0] * iv;
                float oy = Oacc[mf][nf][half * 2 + 1] * iv;
                float rx = ox * (1.0f / (1.0f + __expf(-g0)));
                float ry = oy * (1.0f / (1.0f + __expf(-g1)));
                *(__nv_bfloat162*)(orow + c) = __float22bfloat162_rn(make_float2(rx, ry));
            }
        }
    }
}

// ---------------------------------------------------------------------------
// K3: output projection (tf32 MMA) + transpose + add (proven; at DRAM floor).
// ---------------------------------------------------------------------------
#define A_STRIDE 68
#define B_STRIDE 136

__global__ __launch_bounds__(256) void gemm_out_tc_kernel(
    const float* __restrict__ bo, const float* __restrict__ add,
    float* __restrict__ out)
{
    extern __shared__ unsigned shm[];
    unsigned* As = shm;                  // [128][A_STRIDE]
    unsigned* Ws = shm + 128 * A_STRIDE; // [64][B_STRIDE]

    const int tid  = threadIdx.x;
    const int lane = tid & 31;
    const int w    = tid >> 5;
    const int g    = lane >> 2;
    const int t    = lane & 3;
    const int mw   = (w & 3) * 32;
    const int nw   = (w >> 2) * 64;

    const int m0 = blockIdx.x * 128;

    float acc[2][8][4];
    #pragma unroll
    for (int i = 0; i < 2; i++)
        #pragma unroll
        for (int j = 0; j < 8; j++)
            #pragma unroll
            for (int c = 0; c < 4; c++) acc[i][j][c] = 0.f;

    for (int kc = 0; kc < 128; kc += 64) {
        for (int l = tid; l < 2048; l += 256) {
            int r = l >> 4, c4 = (l & 15) << 2;
            uint2 u = *(const uint2*)&g_attn[(size_t)(m0 + r) * 128 + kc + c4];
            unsigned* d = &As[r * A_STRIDE + c4];
            d[0] = u.x << 16; d[1] = u.x & 0xffff0000u;
            d[2] = u.y << 16; d[3] = u.y & 0xffff0000u;
        }
        for (int l = tid; l < 2048; l += 256) {
            int r = l >> 5, c4 = (l & 31) << 2;
            float4 v = *(const float4*)&g_Wot[(size_t)(kc + r) * 128 + c4];
            unsigned* d = &Ws[r * B_STRIDE + c4];
            d[0] = f2tf(v.x); d[1] = f2tf(v.y); d[2] = f2tf(v.z); d[3] = f2tf(v.w);
        }
        __syncthreads();

        #pragma unroll
        for (int ks = 0; ks < 64; ks += 8) {
            unsigned a[2][4], b[8][2];
            #pragma unroll
            for (int fm = 0; fm < 2; fm++) {
                int r = mw + fm * 16 + g;
                a[fm][0] = As[r * A_STRIDE + ks + t];
                a[fm][1] = As[(r + 8) * A_STRIDE + ks + t];
                a[fm][2] = As[r * A_STRIDE + ks + t + 4];
                a[fm][3] = As[(r + 8) * A_STRIDE + ks + t + 4];
            }
            #pragma unroll
            for (int fn = 0; fn < 8; fn++) {
                int n = nw + fn * 8 + g;
                b[fn][0] = Ws[(ks + t) * B_STRIDE + n];
                b[fn][1] = Ws[(ks + t + 4) * B_STRIDE + n];
            }
            #pragma unroll
            for (int fm = 0; fm < 2; fm++)
                #pragma unroll
                for (int fn = 0; fn < 8; fn++)
                    mma_tf32(acc[fm][fn], a[fm], b[fn]);
        }
        __syncthreads();
    }

    #pragma unroll
    for (int fm = 0; fm < 2; fm++) {
        int m_lo = m0 + mw + fm * 16 + g;
        #pragma unroll
        for (int fn = 0; fn < 8; fn++) {
            int n = nw + fn * 8 + 2 * t;
            float bx = bo[n], by = bo[n + 1];
            {
                int m = m_lo;
                int bb = m >> 8, ss = m & 255;
                size_t base = ((size_t)ss * 256 + bb) * 128 + n;
                float2 av = *(const float2*)&add[base];
                float2 r = { acc[fm][fn][0] + bx + av.x, acc[fm][fn][1] + by + av.y };
                *(float2*)&out[base] = r;
            }
            {
                int m = m_lo + 8;
                int bb = m >> 8, ss = m & 255;
                size_t base = ((size_t)ss * 256 + bb) * 128 + n;
                float2 av = *(const float2*)&add[base];
                float2 r = { acc[fm][fn][2] + bx + av.x, acc[fm][fn][3] + by + av.y };
                *(float2*)&out[base] = r;
            }
        }
    }
}

// ---------------------------------------------------------------------------
extern "C" void kernel_launch(void* const* d_in, const int* in_sizes, int n_in,
                              void* d_out, int out_size)
{
    const float* input_qkv = (const float*)d_in[0];
    const float* mask      = (const float*)d_in[1];
    const float* bias      = (const float*)d_in[2];
    const float* add_to    = (const float*)d_in[3];
    const float* W_qkvg    = (const float*)d_in[4];
    const float* gbias     = (const float*)d_in[5];
    const float* W_o       = (const float*)d_in[6];
    const float* b_o       = (const float*)d_in[7];
    float* out = (float*)d_out;

    // K0: weight prep
    prep_w_kernel<<<(512*128 + 128*128 + 255) / 256, 256>>>(W_qkvg, W_o);

    // K1: QKVG projection (bf16 MMA + ldmatrix)
    {
        const int smem = (128 * KW + 512 * KW) * 4;  // 174080 B
        cudaFuncSetAttribute(gemm_qkvg_bf_kernel,
                             cudaFuncAttributeMaxDynamicSharedMemorySize, smem);
        gemm_qkvg_bf_kernel<<<512, 512, smem>>>(input_qkv);
    }
    // K2: fused attention (bf16 QK^T + ldmatrix, tf32 PV)
    {
        const int smem = (2 * 256 * KQ_STRIDE + 32 * VT_STRIDE
                          + 256 * KS_STRIDE + 256) * 4;   // 113152 B
        cudaFuncSetAttribute(attn_tc_kernel,
                             cudaFuncAttributeMaxDynamicSharedMemorySize, smem);
        dim3 grid(4, 256);
        attn_tc_kernel<<<grid, 256, smem>>>(mask, bias, gbias);
    }
    // K3: output projection (tf32) + transpose + add
    {
        const int gemm_smem = (128 * A_STRIDE + 64 * B_STRIDE) * 4;
        cudaFuncSetAttribute(gemm_out_tc_kernel,
                             cudaFuncAttributeMaxDynamicSharedMemorySize, gemm_smem);
        gemm_out_tc_kernel<<<512, 256, gemm_smem>>>(b_o, add_to, out);
    }
}

// round 14
// speedup vs baseline: 1.0043x; 1.0043x over previous
#include <cuda_runtime.h>
#include <cuda_bf16.h>

#define MTOT (256*256)

// Scratch (static device arrays — no allocation in kernel_launch)
__device__ __nv_bfloat16 g_qkvg[(size_t)MTOT * 512];  // [m][q|k|v|g] bf16
__device__ __nv_bfloat16 g_attn[(size_t)MTOT * 128];  // gated attn out bf16
__device__ __nv_bfloat16 g_Wbf[512 * 128];            // W_qkvg bf16, [n=512][k=128]
__device__ float         g_Wot[128 * 128];            // W_o transposed fp32 [k][n]

// ---------------------------------------------------------------------------
// helpers
// ---------------------------------------------------------------------------
__device__ __forceinline__ unsigned f2tf(float x) {
    unsigned u;
    asm("cvt.rna.tf32.f32 %0, %1;" : "=r"(u) : "f"(x));
    return u;
}
__device__ __forceinline__ float f2tff(float x) { return __uint_as_float(f2tf(x)); }
__device__ __forceinline__ float bf_lo(unsigned w) { return __uint_as_float(w << 16); }
__device__ __forceinline__ float bf_hi(unsigned w) { return __uint_as_float(w & 0xffff0000u); }

__device__ __forceinline__ void mma_tf32(float* d, const unsigned* a, const unsigned* b) {
    asm volatile(
        "mma.sync.aligned.m16n8k8.row.col.f32.tf32.tf32.f32 "
        "{%0,%1,%2,%3}, {%4,%5,%6,%7}, {%8,%9}, {%0,%1,%2,%3};"
        : "+f"(d[0]), "+f"(d[1]), "+f"(d[2]), "+f"(d[3])
        : "r"(a[0]), "r"(a[1]), "r"(a[2]), "r"(a[3]),
          "r"(b[0]), "r"(b[1]));
}
__device__ __forceinline__ void mma_bf16(float* d, const unsigned* a, const unsigned* b) {
    asm volatile(
        "mma.sync.aligned.m16n8k16.row.col.f32.bf16.bf16.f32 "
        "{%0,%1,%2,%3}, {%4,%5,%6,%7}, {%8,%9}, {%0,%1,%2,%3};"
        : "+f"(d[0]), "+f"(d[1]), "+f"(d[2]), "+f"(d[3])
        : "r"(a[0]), "r"(a[1]), "r"(a[2]), "r"(a[3]),
          "r"(b[0]), "r"(b[1]));
}

// ---------------------------------------------------------------------------
// K0: quantize W_qkvg to bf16 + fp32 transpose of W_o.
// ---------------------------------------------------------------------------
__global__ __launch_bounds__(256) void prep_w_kernel(
    const float* __restrict__ W, const float* __restrict__ Wo)
{
    int idx = blockIdx.x * 256 + threadIdx.x;
    if (idx < 512 * 128) {
        g_Wbf[idx] = __float2bfloat16_rn(W[idx]);
    }
    int idx2 = idx - 512 * 128;
    if (idx2 >= 0 && idx2 < 128 * 128) {
        int k = idx2 >> 7;
        int n = idx2 & 127;
        g_Wot[idx2] = Wo[n * 128 + k];
    }
}

// ---------------------------------------------------------------------------
// K1: QKVG projection, bf16 m16n8k16 MMA.
// Block = 64 m-rows x one 256-wide N chunk (blockIdx.y).  Grid (1024, 2).
// smem: As[64][68w] (17.4 KB) + Bs[256][68w] (69.6 KB) = 87 KB -> 2 CTAs/SM.
// 8 warps, warp tile 32x64: mw=(w&1)*32, nw=(w>>1)*64.
// ---------------------------------------------------------------------------
#define KW 68   // 32-bit words per row: 64 data (128 bf16) + 4 pad

__global__ __launch_bounds__(256, 2) void gemm_qkvg_bf_kernel(const float* __restrict__ X)
{
    extern __shared__ unsigned shm[];
    unsigned* As = shm;              // [64][KW]
    unsigned* Bs = shm + 64 * KW;    // [256][KW]

    const int tid  = threadIdx.x;
    const int lane = tid & 31;
    const int w    = tid >> 5;
    const int g    = lane >> 2;
    const int t    = lane & 3;
    const int mw   = (w & 1) * 32;
    const int nw   = (w >> 1) * 64;

    const int m0    = blockIdx.x * 64;
    const int nbase = blockIdx.y * 256;

    // stage A: X fp32 -> bf16x2 words, 64 rows
    for (int l = tid; l < 2048; l += 256) {
        int r = l >> 5, c4 = (l & 31) << 2;
        float4 v = *(const float4*)&X[(size_t)(m0 + r) * 128 + c4];
        __nv_bfloat162 p0 = __float22bfloat162_rn(make_float2(v.x, v.y));
        __nv_bfloat162 p1 = __float22bfloat162_rn(make_float2(v.z, v.w));
        As[r * KW + (c4 >> 1)]     = *(unsigned*)&p0;
        As[r * KW + (c4 >> 1) + 1] = *(unsigned*)&p1;
    }
    // stage B: g_Wbf rows nbase..nbase+255 (128 bf16 = 16 uint4 per row)
    for (int l = tid; l < 4096; l += 256) {
        int n = l >> 4, q = l & 15;
        uint4 v = *(const uint4*)&g_Wbf[(nbase + n) * 128 + q * 8];
        *(uint4*)&Bs[n * KW + q * 4] = v;
    }
    __syncthreads();

    float acc[2][8][4];
    #pragma unroll
    for (int i = 0; i < 2; i++)
        #pragma unroll
        for (int j = 0; j < 8; j++)
            #pragma unroll
            for (int c = 0; c < 4; c++) acc[i][j][c] = 0.f;

    #pragma unroll
    for (int kw = 0; kw < 64; kw += 8) {   // k-step of 16 bf16 (8 words)
        unsigned a[2][4], b[8][2];
        #pragma unroll
        for (int fm = 0; fm < 2; fm++) {
            int r = mw + fm * 16 + g;
            a[fm][0] = As[r * KW + kw + t];
            a[fm][1] = As[(r + 8) * KW + kw + t];
            a[fm][2] = As[r * KW + kw + t + 4];
            a[fm][3] = As[(r + 8) * KW + kw + t + 4];
        }
        #pragma unroll
        for (int fn = 0; fn < 8; fn++) {
            int n = nw + fn * 8 + g;
            b[fn][0] = Bs[n * KW + kw + t];
            b[fn][1] = Bs[n * KW + kw + t + 4];
        }
        #pragma unroll
        for (int fm = 0; fm < 2; fm++)
            #pragma unroll
            for (int fn = 0; fn < 8; fn++)
                mma_bf16(acc[fm][fn], a[fm], b[fn]);
    }

    // epilogue: bf16 stores
    #pragma unroll
    for (int fm = 0; fm < 2; fm++) {
        int row = m0 + mw + fm * 16 + g;
        #pragma unroll
        for (int fn = 0; fn < 8; fn++) {
            int col = nbase + nw + fn * 8 + 2 * t;
            __nv_bfloat162 lo = __float22bfloat162_rn(make_float2(acc[fm][fn][0], acc[fm][fn][1]));
            __nv_bfloat162 hi = __float22bfloat162_rn(make_float2(acc[fm][fn][2], acc[fm][fn][3]));
            *(__nv_bfloat162*)&g_qkvg[(size_t)row * 512 + col] = lo;
            *(__nv_bfloat162*)&g_qkvg[(size_t)(row + 8) * 512 + col] = hi;
        }
    }
}

// ---------------------------------------------------------------------------
// K2: tensor-core fused attention (proven R11 version: tf32 MMA, bf16 I/O).
// ---------------------------------------------------------------------------
#define KS_STRIDE 36
#define VT_STRIDE 268

__global__ __launch_bounds__(256) void attn_tc_kernel(
    const float* __restrict__ mask, const float* __restrict__ bias,
    const float* __restrict__ gbias)
{
    extern __shared__ float sh[];
    float* Ks   = sh;                           // [256][36]
    float* VsT  = sh + 256 * KS_STRIDE;         // [32][268]
    float* Ps   = VsT + 32 * VT_STRIDE;         // [256][36]
    float* madd = Ps + 256 * KS_STRIDE;         // [256]

    const int h = blockIdx.x;
    const int b = blockIdx.y;
    const int tid  = threadIdx.x;
    const int lane = tid & 31;
    const int w    = tid >> 5;
    const int g    = lane >> 2;
    const int t    = lane & 3;
    const int q0   = w * 32;

    {
        const __nv_bfloat16* base = &g_qkvg[(size_t)(b * 256 + tid) * 512 + h * 32];
        #pragma unroll
        for (int j = 0; j < 2; j++) {
            uint4 u = *(const uint4*)(base + 128 + j * 16);
            float* d = &Ks[tid * KS_STRIDE + j * 16];
            d[0] = bf_lo(u.x); d[1]  = bf_hi(u.x);
            d[2] = bf_lo(u.y); d[3]  = bf_hi(u.y);
            d[4] = bf_lo(u.z); d[5]  = bf_hi(u.z);
            d[6] = bf_lo(u.w); d[7]  = bf_hi(u.w);
            uint4 u2 = *(const uint4*)(base + 128 + j * 16 + 8);
            d[8]  = bf_lo(u2.x); d[9]  = bf_hi(u2.x);
            d[10] = bf_lo(u2.y); d[11] = bf_hi(u2.y);
            d[12] = bf_lo(u2.z); d[13] = bf_hi(u2.z);
            d[14] = bf_lo(u2.w); d[15] = bf_hi(u2.w);
        }
        #pragma unroll
        for (int j = 0; j < 4; j++) {
            uint4 u = *(const uint4*)(base + 256 + j * 8);
            VsT[(j * 8 + 0) * VT_STRIDE + tid] = bf_lo(u.x);
            VsT[(j * 8 + 1) * VT_STRIDE + tid] = bf_hi(u.x);
            VsT[(j * 8 + 2) * VT_STRIDE + tid] = bf_lo(u.y);
            VsT[(j * 8 + 3) * VT_STRIDE + tid] = bf_hi(u.y);
            VsT[(j * 8 + 4) * VT_STRIDE + tid] = bf_lo(u.z);
            VsT[(j * 8 + 5) * VT_STRIDE + tid] = bf_hi(u.z);
            VsT[(j * 8 + 6) * VT_STRIDE + tid] = bf_lo(u.w);
            VsT[(j * 8 + 7) * VT_STRIDE + tid] = bf_hi(u.w);
        }
        #pragma unroll
        for (int j = 0; j < 4; j++) {
            uint4 u = *(const uint4*)(base + j * 8);
            float* d = &Ps[tid * KS_STRIDE + j * 8];
            const float s = 0.17677669529663687f;
            d[0] = f2tff(bf_lo(u.x) * s); d[1] = f2tff(bf_hi(u.x) * s);
            d[2] = f2tff(bf_lo(u.y) * s); d[3] = f2tff(bf_hi(u.y) * s);
            d[4] = f2tff(bf_lo(u.z) * s); d[5] = f2tff(bf_hi(u.z) * s);
            d[6] = f2tff(bf_lo(u.w) * s); d[7] = f2tff(bf_hi(u.w) * s);
        }
        madd[tid] = (mask[(size_t)b * 256 + tid] - 1.0f) * 1e9f;
    }
    __syncthreads();

    unsigned Qa[2][4][4];
    #pragma unroll
    for (int mf = 0; mf < 2; mf++) {
        int r = q0 + 16 * mf + g;
        #pragma unroll
        for (int ks = 0; ks < 4; ks++) {
            Qa[mf][ks][0] = __float_as_uint(Ps[r * KS_STRIDE + 8 * ks + t]);
            Qa[mf][ks][1] = __float_as_uint(Ps[(r + 8) * KS_STRIDE + 8 * ks + t]);
            Qa[mf][ks][2] = __float_as_uint(Ps[r * KS_STRIDE + 8 * ks + t + 4]);
            Qa[mf][ks][3] = __float_as_uint(Ps[(r + 8) * KS_STRIDE + 8 * ks + t + 4]);
        }
    }
    __syncwarp();

    float Oacc[2][4][4];
    #pragma unroll
    for (int i = 0; i < 2; i++)
        #pragma unroll
        for (int j = 0; j < 4; j++)
            #pragma unroll
            for (int c = 0; c < 4; c++) Oacc[i][j][c] = 0.f;
    float lsum[4] = {0.f, 0.f, 0.f, 0.f};

    float* Pw = Ps + q0 * KS_STRIDE;
    const float* biasw = &bias[((size_t)h * 256 + q0) * 256];

    for (int k0 = 0; k0 < 256; k0 += 32) {
        float Sacc[2][4][4];
        #pragma unroll
        for (int i = 0; i < 2; i++)
            #pragma unroll
            for (int j = 0; j < 4; j++)
                #pragma unroll
                for (int c = 0; c < 4; c++) Sacc[i][j][c] = 0.f;

        #pragma unroll
        for (int ks = 0; ks < 4; ks++) {
            unsigned bf[4][2];
            #pragma unroll
            for (int nf = 0; nf < 4; nf++) {
                int krow = k0 + 8 * nf + g;
                bf[nf][0] = __float_as_uint(Ks[krow * KS_STRIDE + 8 * ks + t]);
                bf[nf][1] = __float_as_uint(Ks[krow * KS_STRIDE + 8 * ks + t + 4]);
            }
            #pragma unroll
            for (int mf = 0; mf < 2; mf++)
                #pragma unroll
                for (int nf = 0; nf < 4; nf++)
                    mma_tf32(Sacc[mf][nf], Qa[mf][ks], bf[nf]);
        }

        #pragma unroll
        for (int nf = 0; nf < 4; nf++) {
            int col = k0 + 8 * nf + 2 * t;
            float2 md = *(const float2*)&madd[col];
            #pragma unroll
            for (int mf = 0; mf < 2; mf++) {
                int rloc = 16 * mf + g;
                float2 bz0 = *(const float2*)&biasw[(size_t)rloc * 256 + col];
                float2 bz1 = *(const float2*)&biasw[(size_t)(rloc + 8) * 256 + col];
                float p00 = __expf(Sacc[mf][nf][0] + md.x + bz0.x);
                float p01 = __expf(Sacc[mf][nf][1] + md.y + bz0.y);
                float p10 = __expf(Sacc[mf][nf][2] + md.x + bz1.x);
                float p11 = __expf(Sacc[mf][nf][3] + md.y + bz1.y);
                lsum[mf * 2 + 0] += p00 + p01;
                lsum[mf * 2 + 1] += p10 + p11;
                float2 s0 = { f2tff(p00), f2tff(p01) };
                float2 s1 = { f2tff(p10), f2tff(p11) };
                *(float2*)&Pw[rloc * KS_STRIDE + 8 * nf + 2 * t] = s0;
                *(float2*)&Pw[(rloc + 8) * KS_STRIDE + 8 * nf + 2 * t] = s1;
            }
        }
        __syncwarp();

        #pragma unroll
        for (int ks = 0; ks < 4; ks++) {
            unsigned af[2][4], bf[4][2];
            #pragma unroll
            for (int mf = 0; mf < 2; mf++) {
                int rloc = 16 * mf + g;
                af[mf][0] = __float_as_uint(Pw[rloc * KS_STRIDE + 8 * ks + t]);
                af[mf][1] = __float_as_uint(Pw[(rloc + 8) * KS_STRIDE + 8 * ks + t]);
                af[mf][2] = __float_as_uint(Pw[rloc * KS_STRIDE + 8 * ks + t + 4]);
                af[mf][3] = __float_as_uint(Pw[(rloc + 8) * KS_STRIDE + 8 * ks + t + 4]);
            }
            #pragma unroll
            for (int nf = 0; nf < 4; nf++) {
                bf[nf][0] = __float_as_uint(VsT[(8 * nf + g) * VT_STRIDE + k0 + 8 * ks + t]);
                bf[nf][1] = __float_as_uint(VsT[(8 * nf + g) * VT_STRIDE + k0 + 8 * ks + t + 4]);
            }
            #pragma unroll
            for (int mf = 0; mf < 2; mf++)
                #pragma unroll
                for (int nf = 0; nf < 4; nf++)
                    mma_tf32(Oacc[mf][nf], af[mf], bf[nf]);
        }
        __syncwarp();
    }

    float inv[4];
    #pragma unroll
    for (int j = 0; j < 4; j++) {
        float l = lsum[j];
        l += __shfl_xor_sync(0xffffffff, l, 1);
        l += __shfl_xor_sync(0xffffffff, l, 2);
        inv[j] = 1.0f / l;
    }

    #pragma unroll
    for (int mf = 0; mf < 2; mf++) {
        #pragma unroll
        for (int half = 0; half < 2; half++) {
            int r = q0 + 16 * mf + g + half * 8;
            float iv = inv[mf * 2 + half];
            const __nv_bfloat16* grow = &g_qkvg[(size_t)(b * 256 + r) * 512 + 384 + h * 32];
            __nv_bfloat16* orow = &g_attn[(size_t)(b * 256 + r) * 128 + h * 32];
            #pragma unroll
            for (int nf = 0; nf < 4; nf++) {
                int c = 8 * nf + 2 * t;
                unsigned gw = *(const unsigned*)(grow + c);
                float2 gb = *(const float2*)&gbias[h * 32 + c];
                float g0 = bf_lo(gw) + gb.x;
                float g1 = bf_hi(gw) + gb.y;
                float ox = Oacc[mf][nf][half * 2 + 0] * iv;
                float oy = Oacc[mf][nf][half * 2 + 1] * iv;
                float rx = ox * (1.0f / (1.0f + __expf(-g0)));
                float ry = oy * (1.0f / (1.0f + __expf(-g1)));
                *(__nv_bfloat162*)(orow + c) = __float22bfloat162_rn(make_float2(rx, ry));
            }
        }
    }
}

// ---------------------------------------------------------------------------
// K3: output projection (tf32 MMA) + transpose + add (proven R11 version).
// ---------------------------------------------------------------------------
#define A_STRIDE 68
#define B_STRIDE 136

__global__ __launch_bounds__(256) void gemm_out_tc_kernel(
    const float* __restrict__ bo, const float* __restrict__ add,
    float* __restrict__ out)
{
    extern __shared__ unsigned shm[];
    unsigned* As = shm;                  // [128][A_STRIDE]
    unsigned* Ws = shm + 128 * A_STRIDE; // [64][B_STRIDE]

    const int tid  = threadIdx.x;
    const int lane = tid & 31;
    const int w    = tid >> 5;
    const int g    = lane >> 2;
    const int t    = lane & 3;
    const int mw   = (w & 3) * 32;
    const int nw   = (w >> 2) * 64;

    const int m0 = blockIdx.x * 128;

    float acc[2][8][4];
    #pragma unroll
    for (int i = 0; i < 2; i++)
        #pragma unroll
        for (int j = 0; j < 8; j++)
            #pragma unroll
            for (int c = 0; c < 4; c++) acc[i][j][c] = 0.f;

    for (int kc = 0; kc < 128; kc += 64) {
        for (int l = tid; l < 2048; l += 256) {
            int r = l >> 4, c4 = (l & 15) << 2;
            uint2 u = *(const uint2*)&g_attn[(size_t)(m0 + r) * 128 + kc + c4];
            unsigned* d = &As[r * A_STRIDE + c4];
            d[0] = u.x << 16; d[1] = u.x & 0xffff0000u;
            d[2] = u.y << 16; d[3] = u.y & 0xffff0000u;
        }
        for (int l = tid; l < 2048; l += 256) {
            int r = l >> 5, c4 = (l & 31) << 2;
            float4 v = *(const float4*)&g_Wot[(size_t)(kc + r) * 128 + c4];
            unsigned* d = &Ws[r * B_STRIDE + c4];
            d[0] = f2tf(v.x); d[1] = f2tf(v.y); d[2] = f2tf(v.z); d[3] = f2tf(v.w);
        }
        __syncthreads();

        #pragma unroll
        for (int ks = 0; ks < 64; ks += 8) {
            unsigned a[2][4], b[8][2];
            #pragma unroll
            for (int fm = 0; fm < 2; fm++) {
                int r = mw + fm * 16 + g;
                a[fm][0] = As[r * A_STRIDE + ks + t];
                a[fm][1] = As[(r + 8) * A_STRIDE + ks + t];
                a[fm][2] = As[r * A_STRIDE + ks + t + 4];
                a[fm][3] = As[(r + 8) * A_STRIDE + ks + t + 4];
            }
            #pragma unroll
            for (int fn = 0; fn < 8; fn++) {
                int n = nw + fn * 8 + g;
                b[fn][0] = Ws[(ks + t) * B_STRIDE + n];
                b[fn][1] = Ws[(ks + t + 4) * B_STRIDE + n];
            }
            #pragma unroll
            for (int fm = 0; fm < 2; fm++)
                #pragma unroll
                for (int fn = 0; fn < 8; fn++)
                    mma_tf32(acc[fm][fn], a[fm], b[fn]);
        }
        __syncthreads();
    }

    #pragma unroll
    for (int fm = 0; fm < 2; fm++) {
        int m_lo = m0 + mw + fm * 16 + g;
        #pragma unroll
        for (int fn = 0; fn < 8; fn++) {
            int n = nw + fn * 8 + 2 * t;
            float bx = bo[n], by = bo[n + 1];
            {
                int m = m_lo;
                int bb = m >> 8, ss = m & 255;
                size_t base = ((size_t)ss * 256 + bb) * 128 + n;
                float2 av = *(const float2*)&add[base];
                float2 r = { acc[fm][fn][0] + bx + av.x, acc[fm][fn][1] + by + av.y };
                *(float2*)&out[base] = r;
            }
            {
                int m = m_lo + 8;
                int bb = m >> 8, ss = m & 255;
                size_t base = ((size_t)ss * 256 + bb) * 128 + n;
                float2 av = *(const float2*)&add[base];
                float2 r = { acc[fm][fn][2] + bx + av.x, acc[fm][fn][3] + by + av.y };
                *(float2*)&out[base] = r;
            }
        }
    }
}

// ---------------------------------------------------------------------------
extern "C" void kernel_launch(void* const* d_in, const int* in_sizes, int n_in,
                              void* d_out, int out_size)
{
    const float* input_qkv = (const float*)d_in[0];
    const float* mask      = (const float*)d_in[1];
    const float* bias      = (const float*)d_in[2];
    const float* add_to    = (const float*)d_in[3];
    const float* W_qkvg    = (const float*)d_in[4];
    const float* gbias     = (const float*)d_in[5];
    const float* W_o       = (const float*)d_in[6];
    const float* b_o       = (const float*)d_in[7];
    float* out = (float*)d_out;

    // K0: weight prep
    prep_w_kernel<<<(512*128 + 128*128 + 255) / 256, 256>>>(W_qkvg, W_o);

    // K1: QKVG projection (bf16 MMA, 64m x 256n tiles, 2 CTAs/SM)
    {
        const int smem = (64 * KW + 256 * KW) * 4;  // 87040 B
        cudaFuncSetAttribute(gemm_qkvg_bf_kernel,
                             cudaFuncAttributeMaxDynamicSharedMemorySize, smem);
        dim3 grid(1024, 2);
        gemm_qkvg_bf_kernel<<<grid, 256, smem>>>(input_qkv);
    }
    // K2: fused attention (tf32 MMA, bf16 I/O)
    {
        const int smem = (256 * KS_STRIDE + 32 * VT_STRIDE + 256 * KS_STRIDE + 256) * 4;
        cudaFuncSetAttribute(attn_tc_kernel,
                             cudaFuncAttributeMaxDynamicSharedMemorySize, smem);
        dim3 grid(4, 256);
        attn_tc_kernel<<<grid, 256, smem>>>(mask, bias, gbias);
    }
    // K3: output projection (tf32) + transpose + add
    {
        const int gemm_smem = (128 * A_STRIDE + 64 * B_STRIDE) * 4;
        cudaFuncSetAttribute(gemm_out_tc_kernel,
                             cudaFuncAttributeMaxDynamicSharedMemorySize, gemm_smem);
        gemm_out_tc_kernel<<<512, 256, gemm_smem>>>(b_o, add_to, out);
    }
}

// round 15
// speedup vs baseline: 1.0575x; 1.0530x over previous
#include <cuda_runtime.h>
#include <cuda_bf16.h>

#define MTOT (256*256)

// Scratch (static device arrays — no allocation in kernel_launch)
__device__ __nv_bfloat16 g_qkvg[(size_t)MTOT * 512];  // [m][q|k|v|g] bf16
__device__ __nv_bfloat16 g_attn[(size_t)MTOT * 128];  // gated attn out bf16
__device__ __nv_bfloat16 g_Wbf[512 * 128];            // W_qkvg bf16, [n=512][k=128]
__device__ float         g_Wot[128 * 128];            // W_o transposed fp32 [k][n]

// ---------------------------------------------------------------------------
// helpers
// ---------------------------------------------------------------------------
__device__ __forceinline__ unsigned f2tf(float x) {
    unsigned u;
    asm("cvt.rna.tf32.f32 %0, %1;" : "=r"(u) : "f"(x));
    return u;
}
__device__ __forceinline__ float f2tff(float x) { return __uint_as_float(f2tf(x)); }
__device__ __forceinline__ float bf_lo(unsigned w) { return __uint_as_float(w << 16); }
__device__ __forceinline__ float bf_hi(unsigned w) { return __uint_as_float(w & 0xffff0000u); }

__device__ __forceinline__ void mma_tf32(float* d, const unsigned* a, const unsigned* b) {
    asm volatile(
        "mma.sync.aligned.m16n8k8.row.col.f32.tf32.tf32.f32 "
        "{%0,%1,%2,%3}, {%4,%5,%6,%7}, {%8,%9}, {%0,%1,%2,%3};"
        : "+f"(d[0]), "+f"(d[1]), "+f"(d[2]), "+f"(d[3])
        : "r"(a[0]), "r"(a[1]), "r"(a[2]), "r"(a[3]),
          "r"(b[0]), "r"(b[1]));
}
__device__ __forceinline__ void mma_bf16(float* d, const unsigned* a, const unsigned* b) {
    asm volatile(
        "mma.sync.aligned.m16n8k16.row.col.f32.bf16.bf16.f32 "
        "{%0,%1,%2,%3}, {%4,%5,%6,%7}, {%8,%9}, {%0,%1,%2,%3};"
        : "+f"(d[0]), "+f"(d[1]), "+f"(d[2]), "+f"(d[3])
        : "r"(a[0]), "r"(a[1]), "r"(a[2]), "r"(a[3]),
          "r"(b[0]), "r"(b[1]));
}
__device__ __forceinline__ unsigned pack_bf2(float a, float b) {
    __nv_bfloat162 p = __float22bfloat162_rn(make_float2(a, b));
    return *(unsigned*)&p;
}

// ---------------------------------------------------------------------------
// K0: quantize W_qkvg to bf16 + fp32 transpose of W_o.
// ---------------------------------------------------------------------------
__global__ __launch_bounds__(256) void prep_w_kernel(
    const float* __restrict__ W, const float* __restrict__ Wo)
{
    int idx = blockIdx.x * 256 + threadIdx.x;
    if (idx < 512 * 128) {
        g_Wbf[idx] = __float2bfloat16_rn(W[idx]);
    }
    int idx2 = idx - 512 * 128;
    if (idx2 >= 0 && idx2 < 128 * 128) {
        int k = idx2 >> 7;
        int n = idx2 & 127;
        g_Wot[idx2] = Wo[n * 128 + k];
    }
}

// ---------------------------------------------------------------------------
// K1: QKVG projection, bf16 m16n8k16 MMA (R11 shape) + COALESCED epilogue.
// Block = 128 m x N=512 (2 chunks of 256), 512 threads, warp tile 32x64.
// smem: As[128][68w] | Bs[512][68w].  After each chunk's MMAs, the chunk's
// dead Bs half is reused as an epilogue buffer [128 rows][132w]; accumulators
// land there bank-conflict-free, then flow out as full 512B-contiguous rows.
// ---------------------------------------------------------------------------
#define KW 68     // 32-bit words per row: 64 data (128 bf16) + 4 pad
#define EW 132    // epilogue row stride in words: 128 data + 4 pad

__global__ __launch_bounds__(512, 1) void gemm_qkvg_bf_kernel(const float* __restrict__ X)
{
    extern __shared__ unsigned shm[];
    unsigned* As = shm;              // [128][KW]
    unsigned* Bs = shm + 128 * KW;   // [512][KW]

    const int tid  = threadIdx.x;
    const int lane = tid & 31;
    const int w    = tid >> 5;
    const int g    = lane >> 2;
    const int t    = lane & 3;
    const int mw   = (w & 3) * 32;
    const int nw   = (w >> 2) * 64;

    const int m0 = blockIdx.x * 128;

    // stage A: X fp32 -> bf16x2 words
    for (int l = tid; l < 4096; l += 512) {
        int r = l >> 5, c4 = (l & 31) << 2;
        float4 v = *(const float4*)&X[(size_t)(m0 + r) * 128 + c4];
        As[r * KW + (c4 >> 1)]     = pack_bf2(v.x, v.y);
        As[r * KW + (c4 >> 1) + 1] = pack_bf2(v.z, v.w);
    }
    // stage B: g_Wbf rows (128 bf16 = 16 uint4 per row), 512 rows
    for (int l = tid; l < 8192; l += 512) {
        int n = l >> 4, q = l & 15;
        uint4 v = *(const uint4*)&g_Wbf[n * 128 + q * 8];
        *(uint4*)&Bs[n * KW + q * 4] = v;
    }
    __syncthreads();

    #pragma unroll
    for (int chunk = 0; chunk < 2; chunk++) {
        const int nbase = chunk * 256;
        float acc[2][8][4];
        #pragma unroll
        for (int i = 0; i < 2; i++)
            #pragma unroll
            for (int j = 0; j < 8; j++)
                #pragma unroll
                for (int c = 0; c < 4; c++) acc[i][j][c] = 0.f;

        #pragma unroll
        for (int kw = 0; kw < 64; kw += 8) {   // k-step of 16 bf16 (8 words)
            unsigned a[2][4], b[8][2];
            #pragma unroll
            for (int fm = 0; fm < 2; fm++) {
                int r = mw + fm * 16 + g;
                a[fm][0] = As[r * KW + kw + t];
                a[fm][1] = As[(r + 8) * KW + kw + t];
                a[fm][2] = As[r * KW + kw + t + 4];
                a[fm][3] = As[(r + 8) * KW + kw + t + 4];
            }
            #pragma unroll
            for (int fn = 0; fn < 8; fn++) {
                int n = nbase + nw + fn * 8 + g;
                b[fn][0] = Bs[n * KW + kw + t];
                b[fn][1] = Bs[n * KW + kw + t + 4];
            }
            #pragma unroll
            for (int fm = 0; fm < 2; fm++)
                #pragma unroll
                for (int fn = 0; fn < 8; fn++)
                    mma_bf16(acc[fm][fn], a[fm], b[fn]);
        }

        // ---- epilogue: acc -> smem (dead Bs half of this chunk) ----
        __syncthreads();   // all warps done reading this chunk's Bs rows
        unsigned* eb = Bs + nbase * KW;   // 256*KW words >= 128*EW words
        #pragma unroll
        for (int fm = 0; fm < 2; fm++) {
            int r0 = mw + fm * 16 + g;
            #pragma unroll
            for (int fn = 0; fn < 8; fn++) {
                int wd = (nw >> 1) + 4 * fn + t;
                eb[r0 * EW + wd]       = pack_bf2(acc[fm][fn][0], acc[fm][fn][1]);
                eb[(r0 + 8) * EW + wd] = pack_bf2(acc[fm][fn][2], acc[fm][fn][3]);
            }
        }
        __syncthreads();

        // ---- coalesced stores: one row = 512B contiguous (32 lanes x 16B) ----
        #pragma unroll
        for (int i = 0; i < 8; i++) {
            int idx = tid + i * 512;
            int row = idx >> 5, q = idx & 31;
            uint4 v = *(const uint4*)&eb[row * EW + q * 4];
            *(uint4*)&g_qkvg[(size_t)(m0 + row) * 512 + nbase + q * 8] = v;
        }
        // chunk 1 reads only Bs rows 256..511 (untouched); no extra sync needed
    }
}

// ---------------------------------------------------------------------------
// K2: tensor-core fused attention (proven R11 version: tf32 MMA, bf16 I/O).
// ---------------------------------------------------------------------------
#define KS_STRIDE 36
#define VT_STRIDE 268

__global__ __launch_bounds__(256) void attn_tc_kernel(
    const float* __restrict__ mask, const float* __restrict__ bias,
    const float* __restrict__ gbias)
{
    extern __shared__ float sh[];
    float* Ks   = sh;                           // [256][36]
    float* VsT  = sh + 256 * KS_STRIDE;         // [32][268]
    float* Ps   = VsT + 32 * VT_STRIDE;         // [256][36]
    float* madd = Ps + 256 * KS_STRIDE;         // [256]

    const int h = blockIdx.x;
    const int b = blockIdx.y;
    const int tid  = threadIdx.x;
    const int lane = tid & 31;
    const int w    = tid >> 5;
    const int g    = lane >> 2;
    const int t    = lane & 3;
    const int q0   = w * 32;

    {
        const __nv_bfloat16* base = &g_qkvg[(size_t)(b * 256 + tid) * 512 + h * 32];
        #pragma unroll
        for (int j = 0; j < 2; j++) {
            uint4 u = *(const uint4*)(base + 128 + j * 16);
            float* d = &Ks[tid * KS_STRIDE + j * 16];
            d[0] = bf_lo(u.x); d[1]  = bf_hi(u.x);
            d[2] = bf_lo(u.y); d[3]  = bf_hi(u.y);
            d[4] = bf_lo(u.z); d[5]  = bf_hi(u.z);
            d[6] = bf_lo(u.w); d[7]  = bf_hi(u.w);
            uint4 u2 = *(const uint4*)(base + 128 + j * 16 + 8);
            d[8]  = bf_lo(u2.x); d[9]  = bf_hi(u2.x);
            d[10] = bf_lo(u2.y); d[11] = bf_hi(u2.y);
            d[12] = bf_lo(u2.z); d[13] = bf_hi(u2.z);
            d[14] = bf_lo(u2.w); d[15] = bf_hi(u2.w);
        }
        #pragma unroll
        for (int j = 0; j < 4; j++) {
            uint4 u = *(const uint4*)(base + 256 + j * 8);
            VsT[(j * 8 + 0) * VT_STRIDE + tid] = bf_lo(u.x);
            VsT[(j * 8 + 1) * VT_STRIDE + tid] = bf_hi(u.x);
            VsT[(j * 8 + 2) * VT_STRIDE + tid] = bf_lo(u.y);
            VsT[(j * 8 + 3) * VT_STRIDE + tid] = bf_hi(u.y);
            VsT[(j * 8 + 4) * VT_STRIDE + tid] = bf_lo(u.z);
            VsT[(j * 8 + 5) * VT_STRIDE + tid] = bf_hi(u.z);
            VsT[(j * 8 + 6) * VT_STRIDE + tid] = bf_lo(u.w);
            VsT[(j * 8 + 7) * VT_STRIDE + tid] = bf_hi(u.w);
        }
        #pragma unroll
        for (int j = 0; j < 4; j++) {
            uint4 u = *(const uint4*)(base + j * 8);
            float* d = &Ps[tid * KS_STRIDE + j * 8];
            const float s = 0.17677669529663687f;
            d[0] = f2tff(bf_lo(u.x) * s); d[1] = f2tff(bf_hi(u.x) * s);
            d[2] = f2tff(bf_lo(u.y) * s); d[3] = f2tff(bf_hi(u.y) * s);
            d[4] = f2tff(bf_lo(u.z) * s); d[5] = f2tff(bf_hi(u.z) * s);
            d[6] = f2tff(bf_lo(u.w) * s); d[7] = f2tff(bf_hi(u.w) * s);
        }
        madd[tid] = (mask[(size_t)b * 256 + tid] - 1.0f) * 1e9f;
    }
    __syncthreads();

    unsigned Qa[2][4][4];
    #pragma unroll
    for (int mf = 0; mf < 2; mf++) {
        int r = q0 + 16 * mf + g;
        #pragma unroll
        for (int ks = 0; ks < 4; ks++) {
            Qa[mf][ks][0] = __float_as_uint(Ps[r * KS_STRIDE + 8 * ks + t]);
            Qa[mf][ks][1] = __float_as_uint(Ps[(r + 8) * KS_STRIDE + 8 * ks + t]);
            Qa[mf][ks][2] = __float_as_uint(Ps[r * KS_STRIDE + 8 * ks + t + 4]);
            Qa[mf][ks][3] = __float_as_uint(Ps[(r + 8) * KS_STRIDE + 8 * ks + t + 4]);
        }
    }
    __syncwarp();

    float Oacc[2][4][4];
    #pragma unroll
    for (int i = 0; i < 2; i++)
        #pragma unroll
        for (int j = 0; j < 4; j++)
            #pragma unroll
            for (int c = 0; c < 4; c++) Oacc[i][j][c] = 0.f;
    float lsum[4] = {0.f, 0.f, 0.f, 0.f};

    float* Pw = Ps + q0 * KS_STRIDE;
    const float* biasw = &bias[((size_t)h * 256 + q0) * 256];

    for (int k0 = 0; k0 < 256; k0 += 32) {
        float Sacc[2][4][4];
        #pragma unroll
        for (int i = 0; i < 2; i++)
            #pragma unroll
            for (int j = 0; j < 4; j++)
                #pragma unroll
                for (int c = 0; c < 4; c++) Sacc[i][j][c] = 0.f;

        #pragma unroll
        for (int ks = 0; ks < 4; ks++) {
            unsigned bf[4][2];
            #pragma unroll
            for (int nf = 0; nf < 4; nf++) {
                int krow = k0 + 8 * nf + g;
                bf[nf][0] = __float_as_uint(Ks[krow * KS_STRIDE + 8 * ks + t]);
                bf[nf][1] = __float_as_uint(Ks[krow * KS_STRIDE + 8 * ks + t + 4]);
            }
            #pragma unroll
            for (int mf = 0; mf < 2; mf++)
                #pragma unroll
                for (int nf = 0; nf < 4; nf++)
                    mma_tf32(Sacc[mf][nf], Qa[mf][ks], bf[nf]);
        }

        #pragma unroll
        for (int nf = 0; nf < 4; nf++) {
            int col = k0 + 8 * nf + 2 * t;
            float2 md = *(const float2*)&madd[col];
            #pragma unroll
            for (int mf = 0; mf < 2; mf++) {
                int rloc = 16 * mf + g;
                float2 bz0 = *(const float2*)&biasw[(size_t)rloc * 256 + col];
                float2 bz1 = *(const float2*)&biasw[(size_t)(rloc + 8) * 256 + col];
                float p00 = __expf(Sacc[mf][nf][0] + md.x + bz0.x);
                float p01 = __expf(Sacc[mf][nf][1] + md.y + bz0.y);
                float p10 = __expf(Sacc[mf][nf][2] + md.x + bz1.x);
                float p11 = __expf(Sacc[mf][nf][3] + md.y + bz1.y);
                lsum[mf * 2 + 0] += p00 + p01;
                lsum[mf * 2 + 1] += p10 + p11;
                float2 s0 = { f2tff(p00), f2tff(p01) };
                float2 s1 = { f2tff(p10), f2tff(p11) };
                *(float2*)&Pw[rloc * KS_STRIDE + 8 * nf + 2 * t] = s0;
                *(float2*)&Pw[(rloc + 8) * KS_STRIDE + 8 * nf + 2 * t] = s1;
            }
        }
        __syncwarp();

        #pragma unroll
        for (int ks = 0; ks < 4; ks++) {
            unsigned af[2][4], bf[4][2];
            #pragma unroll
            for (int mf = 0; mf < 2; mf++) {
                int rloc = 16 * mf + g;
                af[mf][0] = __float_as_uint(Pw[rloc * KS_STRIDE + 8 * ks + t]);
                af[mf][1] = __float_as_uint(Pw[(rloc + 8) * KS_STRIDE + 8 * ks + t]);
                af[mf][2] = __float_as_uint(Pw[rloc * KS_STRIDE + 8 * ks + t + 4]);
                af[mf][3] = __float_as_uint(Pw[(rloc + 8) * KS_STRIDE + 8 * ks + t + 4]);
            }
            #pragma unroll
            for (int nf = 0; nf < 4; nf++) {
                bf[nf][0] = __float_as_uint(VsT[(8 * nf + g) * VT_STRIDE + k0 + 8 * ks + t]);
                bf[nf][1] = __float_as_uint(VsT[(8 * nf + g) * VT_STRIDE + k0 + 8 * ks + t + 4]);
            }
            #pragma unroll
            for (int mf = 0; mf < 2; mf++)
                #pragma unroll
                for (int nf = 0; nf < 4; nf++)
                    mma_tf32(Oacc[mf][nf], af[mf], bf[nf]);
        }
        __syncwarp();
    }

    float inv[4];
    #pragma unroll
    for (int j = 0; j < 4; j++) {
        float l = lsum[j];
        l += __shfl_xor_sync(0xffffffff, l, 1);
        l += __shfl_xor_sync(0xffffffff, l, 2);
        inv[j] = 1.0f / l;
    }

    #pragma unroll
    for (int mf = 0; mf < 2; mf++) {
        #pragma unroll
        for (int half = 0; half < 2; half++) {
            int r = q0 + 16 * mf + g + half * 8;
            float iv = inv[mf * 2 + half];
            const __nv_bfloat16* grow = &g_qkvg[(size_t)(b * 256 + r) * 512 + 384 + h * 32];
            __nv_bfloat16* orow = &g_attn[(size_t)(b * 256 + r) * 128 + h * 32];
            #pragma unroll
            for (int nf = 0; nf < 4; nf++) {
                int c = 8 * nf + 2 * t;
                unsigned gw = *(const unsigned*)(grow + c);
                float2 gb = *(const float2*)&gbias[h * 32 + c];
                float g0 = bf_lo(gw) + gb.x;
                float g1 = bf_hi(gw) + gb.y;
                float ox = Oacc[mf][nf][half * 2 + 0] * iv;
                float oy = Oacc[mf][nf][half * 2 + 1] * iv;
                float rx = ox * (1.0f / (1.0f + __expf(-g0)));
                float ry = oy * (1.0f / (1.0f + __expf(-g1)));
                *(__nv_bfloat162*)(orow + c) = __float22bfloat162_rn(make_float2(rx, ry));
            }
        }
    }
}

// ---------------------------------------------------------------------------
// K3: output projection (tf32 MMA) + transpose + add (proven R11 version).
// ---------------------------------------------------------------------------
#define A_STRIDE 68
#define B_STRIDE 136

__global__ __launch_bounds__(256) void gemm_out_tc_kernel(
    const float* __restrict__ bo, const float* __restrict__ add,
    float* __restrict__ out)
{
    extern __shared__ unsigned shm[];
    unsigned* As = shm;                  // [128][A_STRIDE]
    unsigned* Ws = shm + 128 * A_STRIDE; // [64][B_STRIDE]

    const int tid  = threadIdx.x;
    const int lane = tid & 31;
    const int w    = tid >> 5;
    const int g    = lane >> 2;
    const int t    = lane & 3;
    const int mw   = (w & 3) * 32;
    const int nw   = (w >> 2) * 64;

    const int m0 = blockIdx.x * 128;

    float acc[2][8][4];
    #pragma unroll
    for (int i = 0; i < 2; i++)
        #pragma unroll
        for (int j = 0; j < 8; j++)
            #pragma unroll
            for (int c = 0; c < 4; c++) acc[i][j][c] = 0.f;

    for (int kc = 0; kc < 128; kc += 64) {
        for (int l = tid; l < 2048; l += 256) {
            int r = l >> 4, c4 = (l & 15) << 2;
            uint2 u = *(const uint2*)&g_attn[(size_t)(m0 + r) * 128 + kc + c4];
            unsigned* d = &As[r * A_STRIDE + c4];
            d[0] = u.x << 16; d[1] = u.x & 0xffff0000u;
            d[2] = u.y << 16; d[3] = u.y & 0xffff0000u;
        }
        for (int l = tid; l < 2048; l += 256) {
            int r = l >> 5, c4 = (l & 31) << 2;
            float4 v = *(const float4*)&g_Wot[(size_t)(kc + r) * 128 + c4];
            unsigned* d = &Ws[r * B_STRIDE + c4];
            d[0] = f2tf(v.x); d[1] = f2tf(v.y); d[2] = f2tf(v.z); d[3] = f2tf(v.w);
        }
        __syncthreads();

        #pragma unroll
        for (int ks = 0; ks < 64; ks += 8) {
            unsigned a[2][4], b[8][2];
            #pragma unroll
            for (int fm = 0; fm < 2; fm++) {
                int r = mw + fm * 16 + g;
                a[fm][0] = As[r * A_STRIDE + ks + t];
                a[fm][1] = As[(r + 8) * A_STRIDE + ks + t];
                a[fm][2] = As[r * A_STRIDE + ks + t + 4];
                a[fm][3] = As[(r + 8) * A_STRIDE + ks + t + 4];
            }
            #pragma unroll
            for (int fn = 0; fn < 8; fn++) {
                int n = nw + fn * 8 + g;
                b[fn][0] = Ws[(ks + t) * B_STRIDE + n];
                b[fn][1] = Ws[(ks + t + 4) * B_STRIDE + n];
            }
            #pragma unroll
            for (int fm = 0; fm < 2; fm++)
                #pragma unroll
                for (int fn = 0; fn < 8; fn++)
                    mma_tf32(acc[fm][fn], a[fm], b[fn]);
        }
        __syncthreads();
    }

    #pragma unroll
    for (int fm = 0; fm < 2; fm++) {
        int m_lo = m0 + mw + fm * 16 + g;
        #pragma unroll
        for (int fn = 0; fn < 8; fn++) {
            int n = nw + fn * 8 + 2 * t;
            float bx = bo[n], by = bo[n + 1];
            {
                int m = m_lo;
                int bb = m >> 8, ss = m & 255;
                size_t base = ((size_t)ss * 256 + bb) * 128 + n;
                float2 av = *(const float2*)&add[base];
                float2 r = { acc[fm][fn][0] + bx + av.x, acc[fm][fn][1] + by + av.y };
                *(float2*)&out[base] = r;
            }
            {
                int m = m_lo + 8;
                int bb = m >> 8, ss = m & 255;
                size_t base = ((size_t)ss * 256 + bb) * 128 + n;
                float2 av = *(const float2*)&add[base];
                float2 r = { acc[fm][fn][2] + bx + av.x, acc[fm][fn][3] + by + av.y };
                *(float2*)&out[base] = r;
            }
        }
    }
}

// ---------------------------------------------------------------------------
extern "C" void kernel_launch(void* const* d_in, const int* in_sizes, int n_in,
                              void* d_out, int out_size)
{
    const float* input_qkv = (const float*)d_in[0];
    const float* mask      = (const float*)d_in[1];
    const float* bias      = (const float*)d_in[2];
    const float* add_to    = (const float*)d_in[3];
    const float* W_qkvg    = (const float*)d_in[4];
    const float* gbias     = (const float*)d_in[5];
    const float* W_o       = (const float*)d_in[6];
    const float* b_o       = (const float*)d_in[7];
    float* out = (float*)d_out;

    // K0: weight prep
    prep_w_kernel<<<(512*128 + 128*128 + 255) / 256, 256>>>(W_qkvg, W_o);

    // K1: QKVG projection (bf16 MMA, coalesced smem epilogue)
    {
        const int smem = (128 * KW + 512 * KW) * 4;  // 174080 B
        cudaFuncSetAttribute(gemm_qkvg_bf_kernel,
                             cudaFuncAttributeMaxDynamicSharedMemorySize, smem);
        gemm_qkvg_bf_kernel<<<512, 512, smem>>>(input_qkv);
    }
    // K2: fused attention (tf32 MMA, bf16 I/O)
    {
        const int smem = (256 * KS_STRIDE + 32 * VT_STRIDE + 256 * KS_STRIDE + 256) * 4;
        cudaFuncSetAttribute(attn_tc_kernel,
                             cudaFuncAttributeMaxDynamicSharedMemorySize, smem);
        dim3 grid(4, 256);
        attn_tc_kernel<<<grid, 256, smem>>>(mask, bias, gbias);
    }
    // K3: output projection (tf32) + transpose + add
    {
        const int gemm_smem = (128 * A_STRIDE + 64 * B_STRIDE) * 4;
        cudaFuncSetAttribute(gemm_out_tc_kernel,
                             cudaFuncAttributeMaxDynamicSharedMemorySize, gemm_smem);
        gemm_out_tc_kernel<<<512, 256, gemm_smem>>>(b_o, add_to, out);
    }
}